// round 4
// baseline (speedup 1.0000x reference)
#include <cuda_runtime.h>

#define NNODES 100000
#define NEDGES 1600000

// ---- scratch (device globals; no allocation allowed) ----
__device__ int   g_counts[NNODES];
__device__ int   g_fill[NNODES];
__device__ int   g_rowptr[NNODES + 1];
__device__ int2  g_edge[NEDGES];          // {src, __float_as_int(w)}
__device__ float g_support[(size_t)NNODES * 64];
__device__ float g_h[(size_t)NNODES * 64];

// ---------------------------------------------------------------- CSR build
__global__ void hist_kernel(const int* __restrict__ tgt) {
    int e = blockIdx.x * blockDim.x + threadIdx.x;
    if (e < NEDGES) atomicAdd(&g_counts[tgt[e]], 1);
}

// single-block exclusive scan over 100k counts -> rowptr; also zeroes g_fill
__global__ void scan_kernel() {
    __shared__ int sums[1024];
    int t = threadIdx.x;
    const int C = (NNODES + 1023) >> 10;   // 98
    int lo = t * C;
    int hi = lo + C; if (hi > NNODES) hi = NNODES;
    int s = 0;
    for (int i = lo; i < hi; i++) s += g_counts[i];
    sums[t] = s;
    __syncthreads();
    for (int off = 1; off < 1024; off <<= 1) {
        int v = sums[t];
        int add = (t >= off) ? sums[t - off] : 0;
        __syncthreads();
        sums[t] = v + add;
        __syncthreads();
    }
    int run = (t == 0) ? 0 : sums[t - 1];
    for (int i = lo; i < hi; i++) {
        g_rowptr[i] = run;
        g_fill[i] = 0;
        run += g_counts[i];
    }
    if (hi == NNODES) g_rowptr[NNODES] = run;   // == NEDGES (idempotent writers)
}

__global__ void scatter_kernel(const int* __restrict__ src,
                               const int* __restrict__ tgt,
                               const float* __restrict__ w) {
    int e = blockIdx.x * blockDim.x + threadIdx.x;
    if (e >= NEDGES) return;
    int t = tgt[e];
    int pos = g_rowptr[t] + atomicAdd(&g_fill[t], 1);
    int2 pk; pk.x = src[e]; pk.y = __float_as_int(w[e]);
    g_edge[pos] = pk;                     // single 8B store
}

// ---------------------------------------------------------------- dense GEMM
// Y[nrows,M] = X[nrows,K] @ W[K,M].  64-row block tile, 4x4 register tile.
// (round-1 proven version)
template <int K, int M>
__global__ void gemm_kernel(const float* __restrict__ X,
                            const float* __restrict__ W,
                            float* __restrict__ Y, int nrows) {
    extern __shared__ float sm[];
    float* Ws = sm;               // K*M
    float* Xs = sm + K * M;       // 64*(K+4), padded vs bank conflicts
    const int nthr = blockDim.x * blockDim.y;
    const int tid  = threadIdx.y * blockDim.x + threadIdx.x;

    for (int i = tid; i < K * M / 4; i += nthr)
        ((float4*)Ws)[i] = ((const float4*)W)[i];

    const int rowBase = blockIdx.x * 64;
    int rlim = nrows - rowBase; if (rlim > 64) rlim = 64;
    const int KV = K / 4;
    for (int i = tid; i < rlim * KV; i += nthr) {
        int r = i / KV, c = i - r * KV;
        float4 v = ((const float4*)X)[(size_t)(rowBase + r) * KV + c];
        *(float4*)&Xs[r * (K + 4) + c * 4] = v;
    }
    __syncthreads();

    const int j  = threadIdx.x * 4;   // blockDim.x = M/4
    const int r0 = threadIdx.y * 4;   // blockDim.y = 16 -> 64 rows
    float acc[4][4];
#pragma unroll
    for (int r = 0; r < 4; r++)
#pragma unroll
        for (int c = 0; c < 4; c++) acc[r][c] = 0.f;

#pragma unroll 8
    for (int k = 0; k < K; k++) {
        float4 wv = *(const float4*)&Ws[k * M + j];
        float x0 = Xs[(r0 + 0) * (K + 4) + k];
        float x1 = Xs[(r0 + 1) * (K + 4) + k];
        float x2 = Xs[(r0 + 2) * (K + 4) + k];
        float x3 = Xs[(r0 + 3) * (K + 4) + k];
        acc[0][0] = fmaf(x0, wv.x, acc[0][0]); acc[0][1] = fmaf(x0, wv.y, acc[0][1]);
        acc[0][2] = fmaf(x0, wv.z, acc[0][2]); acc[0][3] = fmaf(x0, wv.w, acc[0][3]);
        acc[1][0] = fmaf(x1, wv.x, acc[1][0]); acc[1][1] = fmaf(x1, wv.y, acc[1][1]);
        acc[1][2] = fmaf(x1, wv.z, acc[1][2]); acc[1][3] = fmaf(x1, wv.w, acc[1][3]);
        acc[2][0] = fmaf(x2, wv.x, acc[2][0]); acc[2][1] = fmaf(x2, wv.y, acc[2][1]);
        acc[2][2] = fmaf(x2, wv.z, acc[2][2]); acc[2][3] = fmaf(x2, wv.w, acc[2][3]);
        acc[3][0] = fmaf(x3, wv.x, acc[3][0]); acc[3][1] = fmaf(x3, wv.y, acc[3][1]);
        acc[3][2] = fmaf(x3, wv.z, acc[3][2]); acc[3][3] = fmaf(x3, wv.w, acc[3][3]);
    }

#pragma unroll
    for (int r = 0; r < 4; r++) {
        int row = rowBase + r0 + r;
        if (row < nrows) {
            float4 o; o.x = acc[r][0]; o.y = acc[r][1]; o.z = acc[r][2]; o.w = acc[r][3];
            *(float4*)&Y[(size_t)row * M + j] = o;
        }
    }
}

// ----------------------------------------------------- sparse aggregation, M=64
// warp per node; lane owns features (lane, lane+32). Fused bias+relu(+residual).
__global__ void agg64_kernel(const float* __restrict__ sup,
                             const float* __restrict__ bias,
                             float* hout, const float* resid, int has_resid) {
    int gw   = (blockIdx.x * blockDim.x + threadIdx.x) >> 5;
    int lane = threadIdx.x & 31;
    if (gw >= NNODES) return;
    int e   = g_rowptr[gw];
    int end = g_rowptr[gw + 1];
    float a0 = 0.f, a1 = 0.f;
    for (; e + 4 <= end; e += 4) {
        int2 e0 = g_edge[e], e1 = g_edge[e + 1], e2 = g_edge[e + 2], e3 = g_edge[e + 3];
        const float* p0 = sup + (size_t)e0.x * 64;
        const float* p1 = sup + (size_t)e1.x * 64;
        const float* p2 = sup + (size_t)e2.x * 64;
        const float* p3 = sup + (size_t)e3.x * 64;
        float x0 = p0[lane], y0 = p0[lane + 32];
        float x1 = p1[lane], y1 = p1[lane + 32];
        float x2 = p2[lane], y2 = p2[lane + 32];
        float x3 = p3[lane], y3 = p3[lane + 32];
        float w0 = __int_as_float(e0.y), w1 = __int_as_float(e1.y);
        float w2 = __int_as_float(e2.y), w3 = __int_as_float(e3.y);
        a0 = fmaf(x0, w0, a0); a1 = fmaf(y0, w0, a1);
        a0 = fmaf(x1, w1, a0); a1 = fmaf(y1, w1, a1);
        a0 = fmaf(x2, w2, a0); a1 = fmaf(y2, w2, a1);
        a0 = fmaf(x3, w3, a0); a1 = fmaf(y3, w3, a1);
    }
    for (; e < end; e++) {
        int2 ed = g_edge[e];
        const float* p = sup + (size_t)ed.x * 64;
        float w = __int_as_float(ed.y);
        a0 = fmaf(p[lane], w, a0);
        a1 = fmaf(p[lane + 32], w, a1);
    }
    a0 = fmaxf(a0 + bias[lane], 0.f);
    a1 = fmaxf(a1 + bias[lane + 32], 0.f);
    size_t base = (size_t)gw * 64;
    if (has_resid) {               // resid may alias hout: same-element RMW only
        a0 += resid[base + lane];
        a1 += resid[base + lane + 32];
    }
    hout[base + lane]      = a0;
    hout[base + lane + 32] = a1;
}

// ------------------------------------------- sparse aggregation + log_softmax, M=40
__global__ void agg40_kernel(const float* __restrict__ sup,
                             const float* __restrict__ bias,
                             float* __restrict__ out) {
    int gw   = (blockIdx.x * blockDim.x + threadIdx.x) >> 5;
    int lane = threadIdx.x & 31;
    if (gw >= NNODES) return;
    int e   = g_rowptr[gw];
    int end = g_rowptr[gw + 1];
    float a0 = 0.f, a1 = 0.f;
    for (; e + 4 <= end; e += 4) {
        int2 e0 = g_edge[e], e1 = g_edge[e + 1], e2 = g_edge[e + 2], e3 = g_edge[e + 3];
        const float* p0 = sup + (size_t)e0.x * 40;
        const float* p1 = sup + (size_t)e1.x * 40;
        const float* p2 = sup + (size_t)e2.x * 40;
        const float* p3 = sup + (size_t)e3.x * 40;
        float w0 = __int_as_float(e0.y), w1 = __int_as_float(e1.y);
        float w2 = __int_as_float(e2.y), w3 = __int_as_float(e3.y);
        a0 = fmaf(p0[lane], w0, a0);
        a0 = fmaf(p1[lane], w1, a0);
        a0 = fmaf(p2[lane], w2, a0);
        a0 = fmaf(p3[lane], w3, a0);
        if (lane < 8) {
            a1 = fmaf(p0[32 + lane], w0, a1);
            a1 = fmaf(p1[32 + lane], w1, a1);
            a1 = fmaf(p2[32 + lane], w2, a1);
            a1 = fmaf(p3[32 + lane], w3, a1);
        }
    }
    for (; e < end; e++) {
        int2 ed = g_edge[e];
        const float* p = sup + (size_t)ed.x * 40;
        float w = __int_as_float(ed.y);
        a0 = fmaf(p[lane], w, a0);
        if (lane < 8) a1 = fmaf(p[32 + lane], w, a1);
    }
    a0 += bias[lane];
    if (lane < 8) a1 += bias[32 + lane];

    // log_softmax over 40 features distributed over the warp
    float m = a0;
    if (lane < 8) m = fmaxf(m, a1);
#pragma unroll
    for (int o = 16; o; o >>= 1) m = fmaxf(m, __shfl_xor_sync(0xffffffffu, m, o));
    float ssum = __expf(a0 - m) + ((lane < 8) ? __expf(a1 - m) : 0.f);
#pragma unroll
    for (int o = 16; o; o >>= 1) ssum += __shfl_xor_sync(0xffffffffu, ssum, o);
    float L = m + __logf(ssum);

    out[(size_t)gw * 40 + lane] = a0 - L;
    if (lane < 8) out[(size_t)gw * 40 + 32 + lane] = a1 - L;
}

// ---------------------------------------------------------------- launch
static cudaStream_t s_side = nullptr;
static cudaEvent_t  s_evFork = nullptr, s_evJoin = nullptr;

extern "C" void kernel_launch(void* const* d_in, const int* in_sizes, int n_in,
                              void* d_out, int out_size) {
    const float* x   = (const float*)d_in[0];
    const int*   src = (const int*)d_in[1];
    const int*   tgt = (const int*)d_in[2];
    const float* mw  = (const float*)d_in[3];
    const float* W0  = (const float*)d_in[4];  const float* b0 = (const float*)d_in[5];
    const float* W1  = (const float*)d_in[6];  const float* b1 = (const float*)d_in[7];
    const float* W2  = (const float*)d_in[8];  const float* b2 = (const float*)d_in[9];
    const float* W3  = (const float*)d_in[10]; const float* b3 = (const float*)d_in[11];
    float* out = (float*)d_out;

    const int S0 = (128 * 64 + 64 * (128 + 4)) * 4;  // 66560
    const int S1 = (64 * 64 + 64 * (64 + 4)) * 4;    // 33792
    const int S3 = (64 * 40 + 64 * (64 + 4)) * 4;    // 27648

    if (!s_side) {   // one-time host-side init (first call is outside capture)
        cudaStreamCreateWithFlags(&s_side, cudaStreamNonBlocking);
        cudaEventCreateWithFlags(&s_evFork, cudaEventDisableTiming);
        cudaEventCreateWithFlags(&s_evJoin, cudaEventDisableTiming);
        cudaFuncSetAttribute(gemm_kernel<128, 64>, cudaFuncAttributeMaxDynamicSharedMemorySize, S0);
        cudaFuncSetAttribute(gemm_kernel<64, 64>,  cudaFuncAttributeMaxDynamicSharedMemorySize, S1);
        cudaFuncSetAttribute(gemm_kernel<64, 40>,  cudaFuncAttributeMaxDynamicSharedMemorySize, S3);
    }

    void* p;
    cudaGetSymbolAddress(&p, g_support); float* sup = (float*)p;
    cudaGetSymbolAddress(&p, g_h);       float* h   = (float*)p;
    void* pcnt; cudaGetSymbolAddress(&pcnt, g_counts);

    const int gblocks = (NNODES + 63) / 64;
    const int ablocks = ((NNODES * 32) + 255) / 256;

    // ---- fork: CSR build on side stream, overlapped with GEMM-0 ----
    cudaEventRecord(s_evFork, 0);
    cudaStreamWaitEvent(s_side, s_evFork, 0);
    cudaMemsetAsync(pcnt, 0, NNODES * sizeof(int), s_side);
    hist_kernel<<<(NEDGES + 255) / 256, 256, 0, s_side>>>(tgt);
    scan_kernel<<<1, 1024, 0, s_side>>>();
    scatter_kernel<<<(NEDGES + 255) / 256, 256, 0, s_side>>>(src, tgt, mw);
    cudaEventRecord(s_evJoin, s_side);

    // layer 0 GEMM runs concurrently with the CSR build
    gemm_kernel<128, 64><<<gblocks, dim3(16, 16), S0>>>(x, W0, sup, NNODES);
    cudaStreamWaitEvent(0, s_evJoin, 0);   // join before first aggregation

    // layer 0: h = relu(A @ (x W0) + b0)
    agg64_kernel<<<ablocks, 256>>>(sup, b0, h, nullptr, 0);
    // layer 1: h = relu(A @ (h W1) + b1) + h
    gemm_kernel<64, 64><<<gblocks, dim3(16, 16), S1>>>(h, W1, sup, NNODES);
    agg64_kernel<<<ablocks, 256>>>(sup, b1, h, h, 1);
    // layer 2
    gemm_kernel<64, 64><<<gblocks, dim3(16, 16), S1>>>(h, W2, sup, NNODES);
    agg64_kernel<<<ablocks, 256>>>(sup, b2, h, h, 1);
    // layer 3: out = log_softmax(A @ (h W3) + b3)
    gemm_kernel<64, 40><<<gblocks, dim3(10, 16), S3>>>(h, W3, sup, NNODES);
    agg40_kernel<<<ablocks, 256>>>(sup, b3, out);
}

// round 5
// speedup vs baseline: 1.3067x; 1.3067x over previous
#include <cuda_runtime.h>

#define NNODES 100000
#define NEDGES 1600000

// ---- scratch (device globals; no allocation allowed) ----
__device__ int   g_counts[NNODES];
__device__ int   g_fill[NNODES];
__device__ int   g_rowptr[NNODES + 1];
__device__ int2  g_edge[NEDGES];          // {src, __float_as_int(w)}
__device__ float g_support[(size_t)NNODES * 64];
__device__ float g_h[(size_t)NNODES * 64];

// ---------------------------------------------------------------- CSR build
__global__ void zero_counts_kernel() {
    int i = blockIdx.x * blockDim.x + threadIdx.x;
    if (i < NNODES) g_counts[i] = 0;
}

__global__ void hist_kernel(const int* __restrict__ tgt) {
    int e = blockIdx.x * blockDim.x + threadIdx.x;
    if (e < NEDGES) atomicAdd(&g_counts[tgt[e]], 1);
}

// single-block exclusive scan over 100k counts -> rowptr; also zeroes g_fill
__global__ void scan_kernel() {
    __shared__ int sums[1024];
    int t = threadIdx.x;
    const int C = (NNODES + 1023) >> 10;   // 98
    int lo = t * C;
    int hi = lo + C; if (hi > NNODES) hi = NNODES;
    int s = 0;
    for (int i = lo; i < hi; i++) s += g_counts[i];
    sums[t] = s;
    __syncthreads();
    for (int off = 1; off < 1024; off <<= 1) {
        int v = sums[t];
        int add = (t >= off) ? sums[t - off] : 0;
        __syncthreads();
        sums[t] = v + add;
        __syncthreads();
    }
    int run = (t == 0) ? 0 : sums[t - 1];
    for (int i = lo; i < hi; i++) {
        g_rowptr[i] = run;
        g_fill[i] = 0;
        run += g_counts[i];
    }
    if (hi == NNODES) g_rowptr[NNODES] = run;   // == NEDGES (idempotent writers)
}

__global__ void scatter_kernel(const int* __restrict__ src,
                               const int* __restrict__ tgt,
                               const float* __restrict__ w) {
    int e = blockIdx.x * blockDim.x + threadIdx.x;
    if (e >= NEDGES) return;
    int t = tgt[e];
    int pos = g_rowptr[t] + atomicAdd(&g_fill[t], 1);
    int2 pk; pk.x = src[e]; pk.y = __float_as_int(w[e]);
    g_edge[pos] = pk;                     // single 8B store
}

// ---------------------------------------------------------------- dense GEMM
// Y[nrows,M] = X[nrows,K] @ W[K,M].  64-row block tile, 4x4 register tile.
// W staged in K-chunks of 64 rows to keep smem <= ~50KB (occupancy: 4 blocks/SM).
template <int K, int M>
__global__ void gemm_kernel(const float* __restrict__ X,
                            const float* __restrict__ W,
                            float* __restrict__ Y, int nrows) {
    constexpr int KC = (K < 64) ? K : 64;          // W chunk rows
    extern __shared__ float sm[];
    float* Ws = sm;                // KC*M
    float* Xs = sm + KC * M;       // 64*(K+4), padded vs bank conflicts
    const int nthr = blockDim.x * blockDim.y;
    const int tid  = threadIdx.y * blockDim.x + threadIdx.x;

    const int rowBase = blockIdx.x * 64;
    int rlim = nrows - rowBase; if (rlim > 64) rlim = 64;
    const int KV = K / 4;
    for (int i = tid; i < rlim * KV; i += nthr) {
        int r = i / KV, c = i - r * KV;
        float4 v = ((const float4*)X)[(size_t)(rowBase + r) * KV + c];
        *(float4*)&Xs[r * (K + 4) + c * 4] = v;
    }

    const int j  = threadIdx.x * 4;   // blockDim.x = M/4
    const int r0 = threadIdx.y * 4;   // blockDim.y = 16 -> 64 rows
    float acc[4][4];
#pragma unroll
    for (int r = 0; r < 4; r++)
#pragma unroll
        for (int c = 0; c < 4; c++) acc[r][c] = 0.f;

#pragma unroll
    for (int kb = 0; kb < K; kb += KC) {
        if (kb) __syncthreads();                   // prior chunk's compute done
        for (int i = tid; i < KC * M / 4; i += nthr)
            ((float4*)Ws)[i] = ((const float4*)W)[kb * M / 4 + i];
        __syncthreads();                           // Ws (and Xs on first pass) ready

#pragma unroll 8
        for (int kk = 0; kk < KC; kk++) {
            int k = kb + kk;
            float4 wv = *(const float4*)&Ws[kk * M + j];
            float x0 = Xs[(r0 + 0) * (K + 4) + k];
            float x1 = Xs[(r0 + 1) * (K + 4) + k];
            float x2 = Xs[(r0 + 2) * (K + 4) + k];
            float x3 = Xs[(r0 + 3) * (K + 4) + k];
            acc[0][0] = fmaf(x0, wv.x, acc[0][0]); acc[0][1] = fmaf(x0, wv.y, acc[0][1]);
            acc[0][2] = fmaf(x0, wv.z, acc[0][2]); acc[0][3] = fmaf(x0, wv.w, acc[0][3]);
            acc[1][0] = fmaf(x1, wv.x, acc[1][0]); acc[1][1] = fmaf(x1, wv.y, acc[1][1]);
            acc[1][2] = fmaf(x1, wv.z, acc[1][2]); acc[1][3] = fmaf(x1, wv.w, acc[1][3]);
            acc[2][0] = fmaf(x2, wv.x, acc[2][0]); acc[2][1] = fmaf(x2, wv.y, acc[2][1]);
            acc[2][2] = fmaf(x2, wv.z, acc[2][2]); acc[2][3] = fmaf(x2, wv.w, acc[2][3]);
            acc[3][0] = fmaf(x3, wv.x, acc[3][0]); acc[3][1] = fmaf(x3, wv.y, acc[3][1]);
            acc[3][2] = fmaf(x3, wv.z, acc[3][2]); acc[3][3] = fmaf(x3, wv.w, acc[3][3]);
        }
    }

#pragma unroll
    for (int r = 0; r < 4; r++) {
        int row = rowBase + r0 + r;
        if (row < nrows) {
            float4 o; o.x = acc[r][0]; o.y = acc[r][1]; o.z = acc[r][2]; o.w = acc[r][3];
            *(float4*)&Y[(size_t)row * M + j] = o;
        }
    }
}

// ----------------------------------------------------- sparse aggregation, M=64
// warp per node; lane owns features (lane, lane+32). 8-edge unroll for MLP.
// Fused bias+relu(+residual).
__global__ void agg64_kernel(const float* __restrict__ sup,
                             const float* __restrict__ bias,
                             float* hout, const float* resid, int has_resid) {
    int gw   = (blockIdx.x * blockDim.x + threadIdx.x) >> 5;
    int lane = threadIdx.x & 31;
    if (gw >= NNODES) return;
    int e   = g_rowptr[gw];
    int end = g_rowptr[gw + 1];
    float a0 = 0.f, a1 = 0.f;
    for (; e + 8 <= end; e += 8) {
        int2 ed[8];
#pragma unroll
        for (int q = 0; q < 8; q++) ed[q] = g_edge[e + q];
        const float* pp[8];
#pragma unroll
        for (int q = 0; q < 8; q++) pp[q] = sup + (size_t)ed[q].x * 64;
        float xv[8], yv[8];
#pragma unroll
        for (int q = 0; q < 8; q++) { xv[q] = pp[q][lane]; yv[q] = pp[q][lane + 32]; }
#pragma unroll
        for (int q = 0; q < 8; q++) {
            float w = __int_as_float(ed[q].y);
            a0 = fmaf(xv[q], w, a0);
            a1 = fmaf(yv[q], w, a1);
        }
    }
    for (; e < end; e++) {
        int2 ed = g_edge[e];
        const float* p = sup + (size_t)ed.x * 64;
        float w = __int_as_float(ed.y);
        a0 = fmaf(p[lane], w, a0);
        a1 = fmaf(p[lane + 32], w, a1);
    }
    a0 = fmaxf(a0 + bias[lane], 0.f);
    a1 = fmaxf(a1 + bias[lane + 32], 0.f);
    size_t base = (size_t)gw * 64;
    if (has_resid) {               // resid may alias hout: same-element RMW only
        a0 += resid[base + lane];
        a1 += resid[base + lane + 32];
    }
    hout[base + lane]      = a0;
    hout[base + lane + 32] = a1;
}

// ------------------------------------------- sparse aggregation + log_softmax, M=40
__global__ void agg40_kernel(const float* __restrict__ sup,
                             const float* __restrict__ bias,
                             float* __restrict__ out) {
    int gw   = (blockIdx.x * blockDim.x + threadIdx.x) >> 5;
    int lane = threadIdx.x & 31;
    if (gw >= NNODES) return;
    int e   = g_rowptr[gw];
    int end = g_rowptr[gw + 1];
    float a0 = 0.f, a1 = 0.f;
    for (; e + 4 <= end; e += 4) {
        int2 e0 = g_edge[e], e1 = g_edge[e + 1], e2 = g_edge[e + 2], e3 = g_edge[e + 3];
        const float* p0 = sup + (size_t)e0.x * 40;
        const float* p1 = sup + (size_t)e1.x * 40;
        const float* p2 = sup + (size_t)e2.x * 40;
        const float* p3 = sup + (size_t)e3.x * 40;
        float w0 = __int_as_float(e0.y), w1 = __int_as_float(e1.y);
        float w2 = __int_as_float(e2.y), w3 = __int_as_float(e3.y);
        a0 = fmaf(p0[lane], w0, a0);
        a0 = fmaf(p1[lane], w1, a0);
        a0 = fmaf(p2[lane], w2, a0);
        a0 = fmaf(p3[lane], w3, a0);
        if (lane < 8) {
            a1 = fmaf(p0[32 + lane], w0, a1);
            a1 = fmaf(p1[32 + lane], w1, a1);
            a1 = fmaf(p2[32 + lane], w2, a1);
            a1 = fmaf(p3[32 + lane], w3, a1);
        }
    }
    for (; e < end; e++) {
        int2 ed = g_edge[e];
        const float* p = sup + (size_t)ed.x * 40;
        float w = __int_as_float(ed.y);
        a0 = fmaf(p[lane], w, a0);
        if (lane < 8) a1 = fmaf(p[32 + lane], w, a1);
    }
    a0 += bias[lane];
    if (lane < 8) a1 += bias[32 + lane];

    // log_softmax over 40 features distributed over the warp
    float m = a0;
    if (lane < 8) m = fmaxf(m, a1);
#pragma unroll
    for (int o = 16; o; o >>= 1) m = fmaxf(m, __shfl_xor_sync(0xffffffffu, m, o));
    float ssum = __expf(a0 - m) + ((lane < 8) ? __expf(a1 - m) : 0.f);
#pragma unroll
    for (int o = 16; o; o >>= 1) ssum += __shfl_xor_sync(0xffffffffu, ssum, o);
    float L = m + __logf(ssum);

    out[(size_t)gw * 40 + lane] = a0 - L;
    if (lane < 8) out[(size_t)gw * 40 + 32 + lane] = a1 - L;
}

// ---------------------------------------------------------------- launch
extern "C" void kernel_launch(void* const* d_in, const int* in_sizes, int n_in,
                              void* d_out, int out_size) {
    const float* x   = (const float*)d_in[0];
    const int*   src = (const int*)d_in[1];
    const int*   tgt = (const int*)d_in[2];
    const float* mw  = (const float*)d_in[3];
    const float* W0  = (const float*)d_in[4];  const float* b0 = (const float*)d_in[5];
    const float* W1  = (const float*)d_in[6];  const float* b1 = (const float*)d_in[7];
    const float* W2  = (const float*)d_in[8];  const float* b2 = (const float*)d_in[9];
    const float* W3  = (const float*)d_in[10]; const float* b3 = (const float*)d_in[11];
    float* out = (float*)d_out;

    // smem: Ws chunk (KC*M) + Xs (64*(K+4))
    const int S0 = (64 * 64 + 64 * (128 + 4)) * 4;   // 50176 (needs opt-in)
    const int S1 = (64 * 64 + 64 * (64 + 4)) * 4;    // 33792
    const int S3 = (64 * 40 + 64 * (64 + 4)) * 4;    // 27648
    cudaFuncSetAttribute(gemm_kernel<128, 64>, cudaFuncAttributeMaxDynamicSharedMemorySize, S0);

    void* p;
    cudaGetSymbolAddress(&p, g_support); float* sup = (float*)p;
    cudaGetSymbolAddress(&p, g_h);       float* h   = (float*)p;

    // ---- CSR build (serial; fork measured -150us, do not reintroduce) ----
    zero_counts_kernel<<<(NNODES + 255) / 256, 256>>>();
    hist_kernel<<<(NEDGES + 255) / 256, 256>>>(tgt);
    scan_kernel<<<1, 1024>>>();
    scatter_kernel<<<(NEDGES + 255) / 256, 256>>>(src, tgt, mw);

    const int gblocks = (NNODES + 63) / 64;
    const int ablocks = ((NNODES * 32) + 255) / 256;

    // layer 0: h = relu(A @ (x W0) + b0)
    gemm_kernel<128, 64><<<gblocks, dim3(16, 16), S0>>>(x, W0, sup, NNODES);
    agg64_kernel<<<ablocks, 256>>>(sup, b0, h, nullptr, 0);
    // layer 1: h = relu(A @ (h W1) + b1) + h
    gemm_kernel<64, 64><<<gblocks, dim3(16, 16), S1>>>(h, W1, sup, NNODES);
    agg64_kernel<<<ablocks, 256>>>(sup, b1, h, h, 1);
    // layer 2
    gemm_kernel<64, 64><<<gblocks, dim3(16, 16), S1>>>(h, W2, sup, NNODES);
    agg64_kernel<<<ablocks, 256>>>(sup, b2, h, h, 1);
    // layer 3: out = log_softmax(A @ (h W3) + b3)
    gemm_kernel<64, 40><<<gblocks, dim3(10, 16), S3>>>(h, W3, sup, NNODES);
    agg40_kernel<<<ablocks, 256>>>(sup, b3, out);
}